// round 6
// baseline (speedup 1.0000x reference)
#include <cuda_runtime.h>

typedef unsigned long long ull;

#define BN 64    // n rows per block
#define BM 64    // m cols per block
#define TN 4     // n per thread
#define TM 4     // m per thread
#define DD 64    // feature dim
#define C4 16    // DD/4 float4 chunks
#define THREADS 256

// packed accumulate: acc2 += {lo,hi} * 1.0  via fma.rn.f32x2
// (one2 holds {1.0f,1.0f}; mov.b64 pack should be elided by ptxas pair-allocation)
__device__ __forceinline__ void ffma2_acc(ull &acc, float lo, float hi, ull one2) {
    ull t;
    asm("mov.b64 %0, {%1, %2};" : "=l"(t) : "f"(lo), "f"(hi));
    asm("fma.rn.f32x2 %0, %1, %2, %0;" : "+l"(acc) : "l"(t), "l"(one2));
}

__global__ __launch_bounds__(THREADS, 4)
void cdist_l1_kernel(const float4* __restrict__ x4,
                     const float4* __restrict__ w4,
                     float* __restrict__ out,
                     int Mtot)
{
    __shared__ float4 xs[C4][BN];
    __shared__ float4 ws[C4][BM];
    __shared__ float Sx[BN];   // row sums of x tile
    __shared__ float Sw[BM];

    const int tid = threadIdx.x;
    const int n0 = blockIdx.y * BN;
    const int m0 = blockIdx.x * BM;

    // ---- load tiles: 1024 float4 each, 4 per thread ----
    #pragma unroll
    for (int i = 0; i < (BN * C4) / THREADS; i++) {   // 4
        int idx = tid + i * THREADS;
        int n  = idx & (BN - 1);
        int c  = idx >> 6;
        xs[c][n] = x4[(size_t)(n0 + n) * C4 + c];
    }
    #pragma unroll
    for (int i = 0; i < (BM * C4) / THREADS; i++) {   // 4
        int idx = tid + i * THREADS;
        int m  = idx & (BM - 1);
        int c  = idx >> 6;
        ws[c][m] = w4[(size_t)(m0 + m) * C4 + c];
    }
    __syncthreads();

    // ---- per-row sums (one-time) ----
    if (tid < BN) {
        float s = 0.f;
        #pragma unroll
        for (int c = 0; c < C4; c++) {
            float4 v = xs[c][tid];
            s += (v.x + v.y) + (v.z + v.w);
        }
        Sx[tid] = s;
    } else if (tid < BN + BM) {
        int m = tid - BN;
        float s = 0.f;
        #pragma unroll
        for (int c = 0; c < C4; c++) {
            float4 v = ws[c][m];
            s += (v.x + v.y) + (v.z + v.w);
        }
        Sw[m] = s;
    }

    const int tx = tid & 15;   // m: tx + j*16
    const int ty = tid >> 4;   // n: ty*4 + i

    const ull one2 = 0x3F8000003F800000ULL;   // {1.0f, 1.0f}

    // acc2[i][j]: packed pair of partial sums of max(x_d, w_d)
    ull acc2[TN][TM];
    #pragma unroll
    for (int i = 0; i < TN; i++)
        #pragma unroll
        for (int j = 0; j < TM; j++) acc2[i][j] = 0ULL;

    #pragma unroll 4
    for (int c = 0; c < C4; c++) {
        float4 xr[TN], wr[TM];
        #pragma unroll
        for (int i = 0; i < TN; i++) xr[i] = xs[c][ty * TN + i];   // 2-addr broadcast
        #pragma unroll
        for (int j = 0; j < TM; j++) wr[j] = ws[c][j * 16 + tx];   // conflict-free
        // per (i,j): 4 FMNMX (alu, rt2) + 2 FFMA2 (fma) -> 6 issues vs previous 8
        #pragma unroll
        for (int i = 0; i < TN; i++)
            #pragma unroll
            for (int j = 0; j < TM; j++) {
                ffma2_acc(acc2[i][j],
                          fmaxf(xr[i].x, wr[j].x),
                          fmaxf(xr[i].y, wr[j].y), one2);
                ffma2_acc(acc2[i][j],
                          fmaxf(xr[i].z, wr[j].z),
                          fmaxf(xr[i].w, wr[j].w), one2);
            }
    }

    __syncthreads();   // Sx/Sw visibility

    // ---- epilogue: out[n][m] = Sx[n] + Sw[m] - 2*(lo+hi) ----
    float sxr[TN], swr[TM];
    #pragma unroll
    for (int i = 0; i < TN; i++) sxr[i] = Sx[ty * TN + i];
    #pragma unroll
    for (int j = 0; j < TM; j++) swr[j] = Sw[j * 16 + tx];

    #pragma unroll
    for (int i = 0; i < TN; i++) {
        const size_t nrow = (size_t)(n0 + ty * TN + i) * (size_t)Mtot;
        #pragma unroll
        for (int j = 0; j < TM; j++) {
            float lo, hi;
            asm("mov.b64 {%0, %1}, %2;" : "=f"(lo), "=f"(hi) : "l"(acc2[i][j]));
            out[nrow + m0 + j * 16 + tx] = fmaf(-2.f, lo + hi, sxr[i] + swr[j]);
        }
    }
}

extern "C" void kernel_launch(void* const* d_in, const int* in_sizes, int n_in,
                              void* d_out, int out_size) {
    const float4* x4 = (const float4*)d_in[0];   // [N, 64] fp32
    const float4* w4 = (const float4*)d_in[1];   // [M, 64] fp32
    float* out = (float*)d_out;                  // [N, M] fp32

    const int N = in_sizes[0] / DD;   // 8192
    const int M = in_sizes[1] / DD;   // 1024

    dim3 grid(M / BM, N / BN);        // (16, 128)
    cdist_l1_kernel<<<grid, THREADS>>>(x4, w4, out, M);
}

// round 8
// speedup vs baseline: 1.5426x; 1.5426x over previous
#include <cuda_runtime.h>
#include <cuda_fp16.h>

#define BN 64    // n rows per block
#define BM 64    // m cols per block
#define TN 4     // n per thread
#define TM 4     // m per thread
#define DD 64    // feature dim
#define NC 16    // chunks (4 dims each)
#define GRP 4    // chunks per fp32 flush group
#define THREADS 256

// one chunk = 4 dims = 2 half2 = 8 bytes
struct h2pair { __half2 a, b; };

__global__ __launch_bounds__(THREADS, 3)
void cdist_l1_kernel(const float4* __restrict__ x4,
                     const float4* __restrict__ w4,
                     float* __restrict__ out,
                     int Mtot)
{
    __shared__ h2pair xs[NC][BN];   // 8KB
    __shared__ h2pair ws[NC][BM];   // 8KB
    __shared__ float Sx[BN];        // row sums of fp16-rounded x tile (fp32)
    __shared__ float Sw[BM];

    const int tid = threadIdx.x;
    const int n0 = blockIdx.y * BN;
    const int m0 = blockIdx.x * BM;

    // ---- load + convert tiles: 1024 float4 each, 4 per thread ----
    #pragma unroll
    for (int i = 0; i < (BN * NC) / THREADS; i++) {   // 4
        int idx = tid + i * THREADS;
        int n = idx & (BN - 1);
        int c = idx >> 6;
        float4 v = x4[(size_t)(n0 + n) * NC + c];
        h2pair p;
        p.a = __floats2half2_rn(v.x, v.y);
        p.b = __floats2half2_rn(v.z, v.w);
        xs[c][n] = p;
    }
    #pragma unroll
    for (int i = 0; i < (BM * NC) / THREADS; i++) {   // 4
        int idx = tid + i * THREADS;
        int m = idx & (BM - 1);
        int c = idx >> 6;
        float4 v = w4[(size_t)(m0 + m) * NC + c];
        h2pair p;
        p.a = __floats2half2_rn(v.x, v.y);
        p.b = __floats2half2_rn(v.z, v.w);
        ws[c][m] = p;
    }
    __syncthreads();

    // ---- fp32 row sums of the ROUNDED tiles (identity stays exact) ----
    if (tid < BN) {
        float s = 0.f;
        #pragma unroll
        for (int c = 0; c < NC; c++) {
            h2pair p = xs[c][tid];
            float2 fa = __half22float2(p.a);
            float2 fb = __half22float2(p.b);
            s += (fa.x + fa.y) + (fb.x + fb.y);
        }
        Sx[tid] = s;
    } else if (tid < BN + BM) {
        int m = tid - BN;
        float s = 0.f;
        #pragma unroll
        for (int c = 0; c < NC; c++) {
            h2pair p = ws[c][m];
            float2 fa = __half22float2(p.a);
            float2 fb = __half22float2(p.b);
            s += (fa.x + fa.y) + (fb.x + fb.y);
        }
        Sw[m] = s;
    }

    const int tx = tid & 15;   // m: tx + j*16
    const int ty = tid >> 4;   // n: ty*4 + i

    float facc[TN][TM];        // fp32 staged sum of maxes
    #pragma unroll
    for (int i = 0; i < TN; i++)
        #pragma unroll
        for (int j = 0; j < TM; j++) facc[i][j] = 0.f;

    #pragma unroll
    for (int g = 0; g < NC / GRP; g++) {          // 4 groups
        __half2 hacc[TN][TM];                     // per-group fp16 partials
        #pragma unroll
        for (int cc = 0; cc < GRP; cc++) {
            const int c = g * GRP + cc;
            h2pair xr[TN], wr[TM];
            #pragma unroll
            for (int i = 0; i < TN; i++) xr[i] = xs[c][ty * TN + i];  // broadcast
            #pragma unroll
            for (int j = 0; j < TM; j++) wr[j] = ws[c][j * 16 + tx];  // 1-wf LDS.64
            #pragma unroll
            for (int i = 0; i < TN; i++)
                #pragma unroll
                for (int j = 0; j < TM; j++) {
                    // 2 HMAX2 (alu) + HADD2 tree-sum (fma)
                    __half2 t = __hmax2(xr[i].a, wr[j].a);
                    __half2 u = __hmax2(xr[i].b, wr[j].b);
                    __half2 s = __hadd2(t, u);
                    if (cc == 0) hacc[i][j] = s;
                    else         hacc[i][j] = __hadd2(hacc[i][j], s);
                }
        }
        // flush group partial to fp32 (4 issues per (i,j) per group)
        #pragma unroll
        for (int i = 0; i < TN; i++)
            #pragma unroll
            for (int j = 0; j < TM; j++) {
                float2 f = __half22float2(hacc[i][j]);
                facc[i][j] += f.x + f.y;
            }
    }

    __syncthreads();   // Sx/Sw visibility

    // ---- epilogue: out[n][m] = Sx[n] + Sw[m] - 2*sum_max ----
    float sxr[TN], swr[TM];
    #pragma unroll
    for (int i = 0; i < TN; i++) sxr[i] = Sx[ty * TN + i];
    #pragma unroll
    for (int j = 0; j < TM; j++) swr[j] = Sw[j * 16 + tx];

    #pragma unroll
    for (int i = 0; i < TN; i++) {
        const size_t nrow = (size_t)(n0 + ty * TN + i) * (size_t)Mtot;
        #pragma unroll
        for (int j = 0; j < TM; j++) {
            out[nrow + m0 + j * 16 + tx] = fmaf(-2.f, facc[i][j], sxr[i] + swr[j]);
        }
    }
}

extern "C" void kernel_launch(void* const* d_in, const int* in_sizes, int n_in,
                              void* d_out, int out_size) {
    const float4* x4 = (const float4*)d_in[0];   // [N, 64] fp32
    const float4* w4 = (const float4*)d_in[1];   // [M, 64] fp32
    float* out = (float*)d_out;                  // [N, M] fp32

    const int N = in_sizes[0] / DD;   // 8192
    const int M = in_sizes[1] / DD;   // 1024

    dim3 grid(M / BM, N / BN);        // (16, 128)
    cdist_l1_kernel<<<grid, THREADS>>>(x4, w4, out, M);
}

// round 9
// speedup vs baseline: 1.6106x; 1.0441x over previous
#include <cuda_runtime.h>
#include <cuda_fp16.h>

#define BN 64    // n rows per block
#define BM 64    // m cols per block
#define TN 4     // n per thread
#define TM 4     // m per thread
#define DD 64    // feature dim
#define NDC 8    // double-chunks (8 dims = 4 half2 = 16B each)
#define THREADS 256

// 8 dims = 16 bytes -> one LDS.128
struct __align__(16) h2quad { __half2 a, b, c, d; };

__global__ __launch_bounds__(THREADS, 3)
void cdist_l1_kernel(const float4* __restrict__ x4,
                     const float4* __restrict__ w4,
                     float* __restrict__ out,
                     int Mtot)
{
    __shared__ h2quad xs[NDC][BN];   // 8KB
    __shared__ h2quad ws[NDC][BM];   // 8KB
    __shared__ float Sx[BN];         // fp32 row sums of fp16-rounded tiles
    __shared__ float Sw[BM];

    const int tid = threadIdx.x;
    const int n0 = blockIdx.y * BN;
    const int m0 = blockIdx.x * BM;

    // ---- load + convert: each dc = 2 float4 of source ----
    // 2048 float4 total over both tiles, 8 per thread
    #pragma unroll
    for (int i = 0; i < (BN * NDC) / THREADS; i++) {   // 2
        int idx = tid + i * THREADS;                   // over BN*NDC = 512
        int n  = idx & (BN - 1);
        int dc = idx >> 6;
        float4 v0 = x4[(size_t)(n0 + n) * 16 + dc * 2];
        float4 v1 = x4[(size_t)(n0 + n) * 16 + dc * 2 + 1];
        h2quad q;
        q.a = __floats2half2_rn(v0.x, v0.y);
        q.b = __floats2half2_rn(v0.z, v0.w);
        q.c = __floats2half2_rn(v1.x, v1.y);
        q.d = __floats2half2_rn(v1.z, v1.w);
        xs[dc][n] = q;
    }
    #pragma unroll
    for (int i = 0; i < (BM * NDC) / THREADS; i++) {   // 2
        int idx = tid + i * THREADS;
        int m  = idx & (BM - 1);
        int dc = idx >> 6;
        float4 v0 = w4[(size_t)(m0 + m) * 16 + dc * 2];
        float4 v1 = w4[(size_t)(m0 + m) * 16 + dc * 2 + 1];
        h2quad q;
        q.a = __floats2half2_rn(v0.x, v0.y);
        q.b = __floats2half2_rn(v0.z, v0.w);
        q.c = __floats2half2_rn(v1.x, v1.y);
        q.d = __floats2half2_rn(v1.z, v1.w);
        ws[dc][m] = q;
    }
    __syncthreads();

    // ---- fp32 row sums of the ROUNDED tiles ----
    if (tid < BN) {
        float s = 0.f;
        #pragma unroll
        for (int dc = 0; dc < NDC; dc++) {
            h2quad q = xs[dc][tid];
            float2 fa = __half22float2(q.a), fb = __half22float2(q.b);
            float2 fc = __half22float2(q.c), fd = __half22float2(q.d);
            s += ((fa.x + fa.y) + (fb.x + fb.y)) + ((fc.x + fc.y) + (fd.x + fd.y));
        }
        Sx[tid] = s;
    } else if (tid < BN + BM) {
        int m = tid - BN;
        float s = 0.f;
        #pragma unroll
        for (int dc = 0; dc < NDC; dc++) {
            h2quad q = ws[dc][m];
            float2 fa = __half22float2(q.a), fb = __half22float2(q.b);
            float2 fc = __half22float2(q.c), fd = __half22float2(q.d);
            s += ((fa.x + fa.y) + (fb.x + fb.y)) + ((fc.x + fc.y) + (fd.x + fd.y));
        }
        Sw[m] = s;
    }

    const int tx = tid & 15;   // m: tx + j*16
    const int ty = tid >> 4;   // n: ty*4 + i

    float facc[TN][TM];
    #pragma unroll
    for (int i = 0; i < TN; i++)
        #pragma unroll
        for (int j = 0; j < TM; j++) facc[i][j] = 0.f;

    // 4 groups of 2 double-chunks (16 dims per fp16 group -> same precision as R8)
    #pragma unroll
    for (int g = 0; g < NDC / 2; g++) {
        __half2 hacc[TN][TM];
        #pragma unroll
        for (int h = 0; h < 2; h++) {
            const int dc = g * 2 + h;
            h2quad xr[TN], wr[TM];
            #pragma unroll
            for (int i = 0; i < TN; i++) xr[i] = xs[dc][ty * TN + i];  // LDS.128 bcast
            #pragma unroll
            for (int j = 0; j < TM; j++) wr[j] = ws[dc][j * 16 + tx];  // LDS.128 cf
            #pragma unroll
            for (int i = 0; i < TN; i++)
                #pragma unroll
                for (int j = 0; j < TM; j++) {
                    // 4 HMAX2 (alu) + 3 tree HADD2 (fma) per 8 dims
                    __half2 t0 = __hmax2(xr[i].a, wr[j].a);
                    __half2 t1 = __hmax2(xr[i].b, wr[j].b);
                    __half2 t2 = __hmax2(xr[i].c, wr[j].c);
                    __half2 t3 = __hmax2(xr[i].d, wr[j].d);
                    __half2 s  = __hadd2(__hadd2(t0, t1), __hadd2(t2, t3));
                    if (h == 0) hacc[i][j] = s;
                    else        hacc[i][j] = __hadd2(hacc[i][j], s);
                }
        }
        // flush group partial (16 dims) to fp32
        #pragma unroll
        for (int i = 0; i < TN; i++)
            #pragma unroll
            for (int j = 0; j < TM; j++) {
                float2 f = __half22float2(hacc[i][j]);
                facc[i][j] += f.x + f.y;
            }
    }

    __syncthreads();   // Sx/Sw visibility

    // ---- epilogue: out[n][m] = Sx[n] + Sw[m] - 2*sum_max ----
    float sxr[TN], swr[TM];
    #pragma unroll
    for (int i = 0; i < TN; i++) sxr[i] = Sx[ty * TN + i];
    #pragma unroll
    for (int j = 0; j < TM; j++) swr[j] = Sw[j * 16 + tx];

    #pragma unroll
    for (int i = 0; i < TN; i++) {
        const size_t nrow = (size_t)(n0 + ty * TN + i) * (size_t)Mtot;
        #pragma unroll
        for (int j = 0; j < TM; j++) {
            out[nrow + m0 + j * 16 + tx] = fmaf(-2.f, facc[i][j], sxr[i] + swr[j]);
        }
    }
}

extern "C" void kernel_launch(void* const* d_in, const int* in_sizes, int n_in,
                              void* d_out, int out_size) {
    const float4* x4 = (const float4*)d_in[0];   // [N, 64] fp32
    const float4* w4 = (const float4*)d_in[1];   // [M, 64] fp32
    float* out = (float*)d_out;                  // [N, M] fp32

    const int N = in_sizes[0] / DD;   // 8192
    const int M = in_sizes[1] / DD;   // 1024

    dim3 grid(M / BM, N / BN);        // (16, 128)
    cdist_l1_kernel<<<grid, THREADS>>>(x4, w4, out, M);
}

// round 10
// speedup vs baseline: 1.6991x; 1.0549x over previous
#include <cuda_runtime.h>
#include <cuda_fp16.h>

#define BN 128   // n rows per block
#define BM 64    // m cols per block
#define TN 8     // n per thread
#define TM 4     // m per thread
#define DD 64    // feature dim
#define NDC 8    // double-chunks (8 dims = 16B each)
#define BNP (BN + BN / 8)   // padded x rows: slot(n) = n + n/8 (kills 2-way conflict)
#define THREADS 256

struct __align__(16) h2quad { __half2 a, b, c, d; };

// acc = v * 1.0 + acc  -> FFMA-imm (rt_SMSP=1)
__device__ __forceinline__ void ffma_acc1(float &acc, float v) {
    asm("fma.rn.f32 %0, %1, 0f3F800000, %0;" : "+f"(acc) : "f"(v));
}

__global__ __launch_bounds__(THREADS, 2)
void cdist_l1_kernel(const float4* __restrict__ x4,
                     const float4* __restrict__ w4,
                     float* __restrict__ out,
                     int Mtot)
{
    __shared__ h2quad xs[NDC][BNP];  // 18KB (padded)
    __shared__ h2quad ws[NDC][BM];   // 8KB
    __shared__ float Sx[BN];
    __shared__ float Sw[BM];

    const int tid = threadIdx.x;
    const int n0 = blockIdx.y * BN;
    const int m0 = blockIdx.x * BM;

    // ---- load + convert x tile: 1024 (n,dc) items, 4 per thread ----
    #pragma unroll
    for (int i = 0; i < (BN * NDC) / THREADS; i++) {   // 4
        int idx = tid + i * THREADS;
        int n  = idx & (BN - 1);
        int dc = idx >> 7;
        float4 v0 = x4[(size_t)(n0 + n) * 16 + dc * 2];
        float4 v1 = x4[(size_t)(n0 + n) * 16 + dc * 2 + 1];
        h2quad q;
        q.a = __floats2half2_rn(v0.x, v0.y);
        q.b = __floats2half2_rn(v0.z, v0.w);
        q.c = __floats2half2_rn(v1.x, v1.y);
        q.d = __floats2half2_rn(v1.z, v1.w);
        xs[dc][n + (n >> 3)] = q;
    }
    // ---- load + convert w tile: 512 items, 2 per thread ----
    #pragma unroll
    for (int i = 0; i < (BM * NDC) / THREADS; i++) {   // 2
        int idx = tid + i * THREADS;
        int m  = idx & (BM - 1);
        int dc = idx >> 6;
        float4 v0 = w4[(size_t)(m0 + m) * 16 + dc * 2];
        float4 v1 = w4[(size_t)(m0 + m) * 16 + dc * 2 + 1];
        h2quad q;
        q.a = __floats2half2_rn(v0.x, v0.y);
        q.b = __floats2half2_rn(v0.z, v0.w);
        q.c = __floats2half2_rn(v1.x, v1.y);
        q.d = __floats2half2_rn(v1.z, v1.w);
        ws[dc][m] = q;
    }
    __syncthreads();

    // ---- fp32 row sums of the ROUNDED tiles ----
    if (tid < BN) {
        float s = 0.f;
        #pragma unroll
        for (int dc = 0; dc < NDC; dc++) {
            h2quad q = xs[dc][tid + (tid >> 3)];
            float2 fa = __half22float2(q.a), fb = __half22float2(q.b);
            float2 fc = __half22float2(q.c), fd = __half22float2(q.d);
            s += ((fa.x + fa.y) + (fb.x + fb.y)) + ((fc.x + fc.y) + (fd.x + fd.y));
        }
        Sx[tid] = s;
    } else if (tid < BN + BM) {
        int m = tid - BN;
        float s = 0.f;
        #pragma unroll
        for (int dc = 0; dc < NDC; dc++) {
            h2quad q = ws[dc][m];
            float2 fa = __half22float2(q.a), fb = __half22float2(q.b);
            float2 fc = __half22float2(q.c), fd = __half22float2(q.d);
            s += ((fa.x + fa.y) + (fb.x + fb.y)) + ((fc.x + fc.y) + (fd.x + fd.y));
        }
        Sw[m] = s;
    }

    const int tx = tid & 15;   // m: tx + j*16
    const int ty = tid >> 4;   // n: ty*8 + i  (padded slot ty*9 + i)

    float facc[TN][TM];
    #pragma unroll
    for (int i = 0; i < TN; i++)
        #pragma unroll
        for (int j = 0; j < TM; j++) facc[i][j] = 0.f;

    // 4 groups of 2 double-chunks (16 dims per fp16 group, same precision as R9)
    #pragma unroll
    for (int g = 0; g < NDC / 2; g++) {
        __half2 hacc[TN][TM];
        #pragma unroll
        for (int h = 0; h < 2; h++) {
            const int dc = g * 2 + h;
            h2quad xr[TN], wr[TM];
            #pragma unroll
            for (int i = 0; i < TN; i++) xr[i] = xs[dc][ty * 9 + i];   // padded, conflict-free
            #pragma unroll
            for (int j = 0; j < TM; j++) wr[j] = ws[dc][j * 16 + tx];  // conflict-free
            #pragma unroll
            for (int i = 0; i < TN; i++)
                #pragma unroll
                for (int j = 0; j < TM; j++) {
                    __half2 t0 = __hmax2(xr[i].a, wr[j].a);
                    __half2 t1 = __hmax2(xr[i].b, wr[j].b);
                    __half2 t2 = __hmax2(xr[i].c, wr[j].c);
                    __half2 t3 = __hmax2(xr[i].d, wr[j].d);
                    __half2 s  = __hadd2(__hadd2(t0, t1), __hadd2(t2, t3));
                    if (h == 0) hacc[i][j] = s;
                    else        hacc[i][j] = __hadd2(hacc[i][j], s);
                }
        }
        // flush 16-dim partial to fp32 (2x FFMA-imm per pair)
        #pragma unroll
        for (int i = 0; i < TN; i++)
            #pragma unroll
            for (int j = 0; j < TM; j++) {
                float2 f = __half22float2(hacc[i][j]);
                ffma_acc1(facc[i][j], f.x);
                ffma_acc1(facc[i][j], f.y);
            }
    }

    __syncthreads();   // Sx/Sw visibility

    // ---- epilogue: out[n][m] = Sx[n] + Sw[m] - 2*sum_max ----
    float sxr[TN], swr[TM];
    #pragma unroll
    for (int i = 0; i < TN; i++) sxr[i] = Sx[ty * TN + i];
    #pragma unroll
    for (int j = 0; j < TM; j++) swr[j] = Sw[j * 16 + tx];

    #pragma unroll
    for (int i = 0; i < TN; i++) {
        const size_t nrow = (size_t)(n0 + ty * TN + i) * (size_t)Mtot;
        #pragma unroll
        for (int j = 0; j < TM; j++) {
            out[nrow + m0 + j * 16 + tx] = fmaf(-2.f, facc[i][j], sxr[i] + swr[j]);
        }
    }
}

extern "C" void kernel_launch(void* const* d_in, const int* in_sizes, int n_in,
                              void* d_out, int out_size) {
    const float4* x4 = (const float4*)d_in[0];   // [N, 64] fp32
    const float4* w4 = (const float4*)d_in[1];   // [M, 64] fp32
    float* out = (float*)d_out;                  // [N, M] fp32

    const int N = in_sizes[0] / DD;   // 8192
    const int M = in_sizes[1] / DD;   // 1024

    dim3 grid(M / BM, N / BN);        // (16, 64)
    cdist_l1_kernel<<<grid, THREADS>>>(x4, w4, out, M);
}